// round 14
// baseline (speedup 1.0000x reference)
#include <cuda_runtime.h>
#include <cstdint>

#define TSTEPS  1024
#define FEAT    64
#define UNITS   256
#define FOURU   1024
#define KQ      64        // K rows per k-quarter (K = 256, h only)
#define NCOLS   128       // gate-columns per CTA: 32 units x 4 gates
#define CLUSTER 8
#define RTHREADS 512
#define BB      32        // batch rows per cluster
#define NCLUST  16
#define HROW    32        // floats per h row (32 batches)
#define HSKEW   8         // +8 floats per 64-row chunk (bank decorrelation)
#define HBUF_F  (UNITS * HROW + 4 * HSKEW)   // 8224 floats per h buffer
#define SLAB_F  (32 * 32)                    // 1024 floats = 4096 B
#define EXPECT_BYTES (CLUSTER * SLAB_F * 4)  // 32768 B per inbox phase

#define ZXT 512           // zx block threads
#define ZXROWS 256        // t-rows per zx block
#define XS_STR 260        // xs row stride (256 + 4 pad)

// z_x scratch: zx[t][b][c], c = unit*4 + gate, bias folded in. Two 1 GB halves.
__device__ float g_zxA[(size_t)512 * 512 * 1024];
__device__ float g_zxB[(size_t)512 * 512 * 1024];

// ---------- packed f32x2 helpers ----------
__device__ __forceinline__ unsigned long long dup2(float x) {
    unsigned long long r; uint32_t u = __float_as_uint(x);
    asm("mov.b64 %0, {%1, %1};" : "=l"(r) : "r"(u));
    return r;
}
__device__ __forceinline__ void fma2(unsigned long long& d,
                                     unsigned long long a,
                                     unsigned long long b) {
    asm("fma.rn.f32x2 %0, %1, %2, %0;" : "+l"(d) : "l"(a), "l"(b));
}
__device__ __forceinline__ float2 up2(unsigned long long v) {
    float2 r;
    asm("mov.b64 {%0, %1}, %2;" : "=f"(r.x), "=f"(r.y) : "l"(v));
    return r;
}
__device__ __forceinline__ unsigned long long xadd(unsigned long long v, int m) {
    uint32_t lo, hi;
    asm("mov.b64 {%0,%1}, %2;" : "=r"(lo), "=r"(hi) : "l"(v));
    lo = __shfl_xor_sync(0xffffffffu, lo, m);
    hi = __shfl_xor_sync(0xffffffffu, hi, m);
    unsigned long long o;
    asm("mov.b64 %0, {%1,%2};" : "=l"(o) : "r"(lo), "r"(hi));
    asm("add.rn.f32x2 %0, %0, %1;" : "+l"(v) : "l"(o));
    return v;
}
__device__ __forceinline__ float fsig(float x) {
    return __fdividef(1.0f, 1.0f + __expf(-x));
}
__device__ __forceinline__ float ftanh(float x) {
    return fmaf(2.0f, fsig(2.0f * x), -1.0f);
}
__device__ __forceinline__ void mbar_wait(uint32_t mbar, uint32_t parity) {
    uint32_t done;
    do {
        asm volatile(
            "{\n\t.reg .pred P;\n\t"
            "mbarrier.try_wait.parity.acquire.cluster.shared::cta.b64 P, [%1], %2, 0x989680;\n\t"
            "selp.b32 %0, 1, 0, P;\n\t}"
            : "=r"(done) : "r"(mbar), "r"(parity) : "memory");
    } while (!done);
}

// ============================================================================
// Kernel 1: zx = x @ W(perm) + bias(perm). 512 thr (4 warps/SMSP), block
// covers 256 t-rows x 128 cols; per-thread tile 8t x 8c (identical math to
// the proven R9 version; only ty range / xs stride / grid changed).
// grid (8 col-tiles, 4 t-tiles, 512 b). Dynamic smem ~100 KB.
// ============================================================================
__global__ void __launch_bounds__(ZXT)
zx_kernel(const float* __restrict__ x, const float* __restrict__ W,
          const float* __restrict__ bias)
{
    extern __shared__ float zsm[];
    float* ws = zsm;                  // [64][132]  33792 B
    float* xs = zsm + 64 * 132;       // [64][260]  66560 B

    const int tid = threadIdx.x;
    const int cb  = blockIdx.x;       // 128-col tile (0..7)
    const int tb  = blockIdx.y;       // 256-t tile (0..3)
    const int b   = blockIdx.z;       // batch (0..511)

    // stage W tile (permuted cols): ws[k][cc]
    for (int idx = tid; idx < 64 * 128; idx += ZXT) {
        const int k = idx >> 7, cc = idx & 127;
        const int c = cb * 128 + cc;
        ws[k * 132 + cc] = W[(size_t)k * FOURU + (c & 3) * UNITS + (c >> 2)];
    }
    // stage x tile transposed: xs[k][tt], tt in [0,256)
    {
        const float* xb = x + ((size_t)b * TSTEPS + tb * ZXROWS) * FEAT;
        for (int idx = tid; idx < ZXROWS * 16; idx += ZXT) {
            const int tt = idx >> 4, k4 = idx & 15;
            const float4 v = *(const float4*)(xb + (size_t)tt * FEAT + k4 * 4);
            xs[(k4 * 4 + 0) * XS_STR + tt] = v.x;
            xs[(k4 * 4 + 1) * XS_STR + tt] = v.y;
            xs[(k4 * 4 + 2) * XS_STR + tt] = v.z;
            xs[(k4 * 4 + 3) * XS_STR + tt] = v.w;
        }
    }
    __syncthreads();

    const int tx = tid & 15;          // col-oct (8 cols)
    const int ty = tid >> 4;          // t-oct (8 rows), 0..31

    unsigned long long acc[8][4];
    {
        unsigned long long bp[4];
        #pragma unroll
        for (int j = 0; j < 4; j++) {
            const int ca = cb * 128 + tx * 8 + 2 * j;
            const int cbn = ca + 1;
            uint32_t lo = __float_as_uint(bias[(ca  & 3) * UNITS + (ca  >> 2)]);
            uint32_t hi = __float_as_uint(bias[(cbn & 3) * UNITS + (cbn >> 2)]);
            unsigned long long r;
            asm("mov.b64 %0, {%1,%2};" : "=l"(r) : "r"(lo), "r"(hi));
            bp[j] = r;
        }
        #pragma unroll
        for (int i = 0; i < 8; i++)
            #pragma unroll
            for (int j = 0; j < 4; j++) acc[i][j] = bp[j];
    }

    #pragma unroll 4
    for (int k = 0; k < 64; k++) {
        const float4 a0 = *(const float4*)(xs + k * XS_STR + ty * 8);
        const float4 a1 = *(const float4*)(xs + k * XS_STR + ty * 8 + 4);
        const ulonglong2 w0 = *(const ulonglong2*)(ws + k * 132 + tx * 8);
        const ulonglong2 w1 = *(const ulonglong2*)(ws + k * 132 + tx * 8 + 4);
        const unsigned long long wv[4] = { w0.x, w0.y, w1.x, w1.y };
        const unsigned long long ad[8] = { dup2(a0.x), dup2(a0.y), dup2(a0.z), dup2(a0.w),
                                           dup2(a1.x), dup2(a1.y), dup2(a1.z), dup2(a1.w) };
        #pragma unroll
        for (int i = 0; i < 8; i++)
            #pragma unroll
            for (int j = 0; j < 4; j++)
                fma2(acc[i][j], ad[i], wv[j]);
    }

    #pragma unroll
    for (int i = 0; i < 8; i++) {
        const int t = tb * ZXROWS + ty * 8 + i;
        float* o = ((t < 512) ? g_zxA : g_zxB) +
                   ((size_t)(t & 511) * 512 + b) * FOURU + cb * 128 + tx * 8;
        const float2 p0 = up2(acc[i][0]), p1 = up2(acc[i][1]);
        const float2 p2 = up2(acc[i][2]), p3 = up2(acc[i][3]);
        *(float4*)(o)     = make_float4(p0.x, p0.y, p1.x, p1.y);
        *(float4*)(o + 4) = make_float4(p2.x, p2.y, p3.x, p3.y);
    }
}

// ============================================================================
// Kernel 2 (R11/R8, measured 13.08ms): recurrent LSTM. UNCHANGED.
// 16 clusters x 8 CTAs x 512 thr. Uh slice in SMEM; thread = 8 batches x
// 4 gates over K-quarter; butterfly reduce over kq lanes; h exchanged via
// slab + 8 cp.async.bulk per CTA/step into double-buffered bank-skewed h
// buffers (single inbox mbarrier per buffer). Epilogue: softmax over the
// size-1 axis == 1 -> out[b,:] = sigmoid(h_T . dw + db).
// ============================================================================
extern "C" __global__ void __launch_bounds__(RTHREADS, 1) __cluster_dims__(CLUSTER, 1, 1)
lstm_kernel(const float* __restrict__ Uh, const float* __restrict__ dw,
            const float* __restrict__ db, float* __restrict__ out)
{
    extern __shared__ float smem[];
    float* Uc   = smem;                              // [256][128] 131072 B
    float* hb   = smem + UNITS * NCOLS;              // 2 x 8224 floats
    float* slab = hb + 2 * HBUF_F;                   // 2 x 1024 floats

    const int tid = threadIdx.x;
    uint32_t rank, cid;
    asm("mov.u32 %0, %%cluster_ctarank;" : "=r"(rank));
    asm("mov.u32 %0, %%clusterid.x;"     : "=r"(cid));

    uint32_t smem_u32;
    asm("{ .reg .u64 t0; cvta.to.shared.u64 t0, %1; cvt.u32.u64 %0, t0; }"
        : "=r"(smem_u32) : "l"(smem));
    const uint32_t hb_u32    = smem_u32 + UNITS * NCOLS * 4;
    const uint32_t slab_u32  = hb_u32 + 2 * HBUF_F * 4;
    const uint32_t inbox_u32 = slab_u32 + 2 * SLAB_F * 4;   // 2 mbarriers

    for (int idx = tid; idx < UNITS * NCOLS; idx += RTHREADS) {
        const int k = idx >> 7, c = idx & 127;
        const int gcol = (c & 3) * UNITS + (int)rank * 32 + (c >> 2);
        Uc[idx] = Uh[(size_t)k * FOURU + gcol];
    }
    for (int i = tid; i < 2 * HBUF_F; i += RTHREADS) hb[i] = 0.0f;
    if (tid == 0) {
        asm volatile("mbarrier.init.shared.b64 [%0], 1;" :: "r"(inbox_u32)     : "memory");
        asm volatile("mbarrier.init.shared.b64 [%0], 1;" :: "r"(inbox_u32 + 8) : "memory");
    }
    __syncthreads();
    asm volatile("barrier.cluster.arrive.aligned;" ::: "memory");
    asm volatile("barrier.cluster.wait.aligned;"   ::: "memory");

    const int wid  = tid >> 5, lane = tid & 31;
    const int ugq  = wid & 3;        // unit group (8 units)
    const int bq   = wid >> 2;       // batch group (8 batches), 0..3
    const int kq   = lane >> 3;      // K quarter
    const int u8   = lane & 7;
    const int unit = ugq * 8 + u8;   // local unit 0..31

    uint32_t dstb[CLUSTER], mbb[CLUSTER];
    {
        const uint32_t my_hoff = (uint32_t)(((int)rank * 1024 + ((int)rank >> 1) * HSKEW) * 4);
        #pragma unroll
        for (int r = 0; r < CLUSTER; r++) {
            asm("mapa.shared::cluster.u32 %0, %1, %2;" : "=r"(dstb[r]) : "r"(hb_u32 + my_hoff), "r"(r));
            asm("mapa.shared::cluster.u32 %0, %1, %2;" : "=r"(mbb[r])  : "r"(inbox_u32),        "r"(r));
        }
    }

    const int bloc = bq * 8 + kq * 2;                         // my 2 batches (local)
    const int b0   = (int)cid * BB + bloc;                    // global
    const int cb   = ((int)rank * 32 + unit) * 4;             // zx column base

    const float4* ucp = (const float4*)(Uc + unit * 4 + (kq * KQ) * NCOLS);
    const ulonglong2* apb = (const ulonglong2*)(hb + (kq * KQ) * HROW + kq * HSKEW + bq * 8);

    float cst[2] = {0.f, 0.f};

    float4 zc[2];
    #pragma unroll
    for (int j = 0; j < 2; j++)
        zc[j] = *(const float4*)(g_zxA + (size_t)(b0 + j) * FOURU + cb);

    for (int t = 0; t < TSTEPS; t++) {
        if (tid == 0) {
            asm volatile("mbarrier.arrive.expect_tx.shared.b64 _, [%0], %1;"
                :: "r"(inbox_u32 + (uint32_t)(((t + 1) & 1) * 8)),
                   "r"((uint32_t)EXPECT_BYTES) : "memory");
        }
        float4 zn[2];
        #pragma unroll
        for (int j = 0; j < 2; j++) zn[j] = zc[j];
        if (t < TSTEPS - 1) {
            const int tn = t + 1;
            const float* zp = ((tn < 512) ? g_zxA : g_zxB) +
                              ((size_t)(tn & 511) * 512 + b0) * FOURU + cb;
            #pragma unroll
            for (int j = 0; j < 2; j++) zn[j] = *(const float4*)(zp + (size_t)j * FOURU);
        }
        if (t > 0)
            mbar_wait(inbox_u32 + (uint32_t)((t & 1) * 8),
                      (uint32_t)(((t - 1) >> 1) & 1));

        unsigned long long acc[4][4];
        #pragma unroll
        for (int p = 0; p < 4; p++)
            #pragma unroll
            for (int g = 0; g < 4; g++) acc[p][g] = 0ull;

        const ulonglong2* ap = (const ulonglong2*)((const char*)apb +
                               (size_t)(t & 1) * (HBUF_F * 4));
        #pragma unroll 4
        for (int kk = 0; kk < KQ; kk++) {
            const float4 u4 = ucp[kk * 32];
            const unsigned long long ug[4] = { dup2(u4.x), dup2(u4.y),
                                               dup2(u4.z), dup2(u4.w) };
            const ulonglong2 a0 = ap[kk * 8 + 0];
            const ulonglong2 a1 = ap[kk * 8 + 1];
            const unsigned long long av[4] = { a0.x, a0.y, a1.x, a1.y };
            #pragma unroll
            for (int p = 0; p < 4; p++)
                #pragma unroll
                for (int g = 0; g < 4; g++)
                    fma2(acc[p][g], av[p], ug[g]);
        }

        #pragma unroll
        for (int p = 0; p < 4; p++)
            #pragma unroll
            for (int g = 0; g < 4; g++) {
                acc[p][g] = xadd(acc[p][g], 8);
                acc[p][g] = xadd(acc[p][g], 16);
            }

        const bool m1 = (kq >= 2), m0 = (kq & 1);
        unsigned long long zA[4];
        #pragma unroll
        for (int g = 0; g < 4; g++) {
            const unsigned long long s0 = m1 ? acc[2][g] : acc[0][g];
            const unsigned long long s1 = m1 ? acc[3][g] : acc[1][g];
            zA[g] = m0 ? s1 : s0;
        }

        const float2 zi = up2(zA[0]);
        const float2 zf = up2(zA[1]);
        const float2 zg = up2(zA[2]);
        const float2 zo = up2(zA[3]);
        float h0v, h1v;
        {
            const float ig = fsig(zi.x + zc[0].x), fg = fsig(zf.x + zc[0].y);
            const float gg = ftanh(zg.x + zc[0].z), og = fsig(zo.x + zc[0].w);
            cst[0] = fmaf(fg, cst[0], ig * gg);
            h0v    = og * ftanh(cst[0]);
        }
        {
            const float ig = fsig(zi.y + zc[1].x), fg = fsig(zf.y + zc[1].y);
            const float gg = ftanh(zg.y + zc[1].z), og = fsig(zo.y + zc[1].w);
            cst[1] = fmaf(fg, cst[1], ig * gg);
            h1v    = og * ftanh(cst[1]);
        }

        *(float2*)(slab + ((t + 1) & 1) * SLAB_F + unit * 32 + bloc) =
            make_float2(h0v, h1v);
        __syncthreads();
        if (tid == 0) {
            asm volatile("fence.proxy.async.shared::cta;" ::: "memory");
            const uint32_t src  = slab_u32 + (uint32_t)(((t + 1) & 1) * SLAB_F * 4);
            const uint32_t doff = (uint32_t)(((t + 1) & 1) * HBUF_F * 4);
            const uint32_t moff = (uint32_t)(((t + 1) & 1) * 8);
            #pragma unroll
            for (int r = 0; r < CLUSTER; r++) {
                asm volatile(
                    "cp.async.bulk.shared::cluster.shared::cta.mbarrier::complete_tx::bytes "
                    "[%0], [%1], %2, [%3];"
                    :: "r"(dstb[r] + doff), "r"(src), "r"((uint32_t)(SLAB_F * 4)),
                       "r"(mbb[r] + moff) : "memory");
            }
        }
        #pragma unroll
        for (int j = 0; j < 2; j++) zc[j] = zn[j];
    }

    mbar_wait(inbox_u32, (uint32_t)(((TSTEPS - 1) >> 1) & 1));
    asm volatile("barrier.cluster.arrive.aligned;" ::: "memory");

    {
        const int bl = (int)rank * 4 + (wid & 3);     // local batch 0..31
        float s = 0.0f;
        for (int u = lane; u < UNITS; u += 32)
            s += hb[u * HROW + (u >> 6) * HSKEW + bl] * dw[u];
        #pragma unroll
        for (int o = 16; o > 0; o >>= 1)
            s += __shfl_xor_sync(0xffffffffu, s, o);
        const float val = fsig(s + db[0]);
        float* op = out + ((size_t)cid * BB + bl) * TSTEPS + (wid >> 2) * 256;
        for (int i = lane; i < 256; i += 32)
            op[i] = val;
    }
    asm volatile("barrier.cluster.wait.aligned;" ::: "memory");
}

extern "C" void kernel_launch(void* const* d_in, const int* in_sizes, int n_in,
                              void* d_out, int out_size)
{
    const float* x  = (const float*)d_in[0];
    const float* W  = (const float*)d_in[1];
    const float* Uh = (const float*)d_in[2];
    const float* b  = (const float*)d_in[3];
    const float* dw = (const float*)d_in[4];
    const float* db = (const float*)d_in[5];
    float* out = (float*)d_out;

    const size_t zsm = (size_t)(64 * 132 + 64 * XS_STR) * sizeof(float);
    cudaFuncSetAttribute(zx_kernel,
                         cudaFuncAttributeMaxDynamicSharedMemorySize, (int)zsm);
    zx_kernel<<<dim3(8, 4, 512), ZXT, zsm>>>(x, W, b);

    const size_t rsm = (size_t)(UNITS * NCOLS + 2 * HBUF_F + 2 * SLAB_F) * sizeof(float) + 32;
    cudaFuncSetAttribute(lstm_kernel,
                         cudaFuncAttributeMaxDynamicSharedMemorySize, (int)rsm);
    lstm_kernel<<<NCLUST * CLUSTER, RTHREADS, rsm>>>(Uh, dw, db, out);
}

// round 15
// speedup vs baseline: 1.0219x; 1.0219x over previous
#include <cuda_runtime.h>
#include <cstdint>

#define TSTEPS  1024
#define FEAT    64
#define UNITS   256
#define FOURU   1024
#define KQ      64        // K rows per k-quarter (K = 256, h only)
#define NCOLS   128       // gate-columns per CTA: 32 units x 4 gates
#define CLUSTER 8
#define RTHREADS 512
#define BB      32        // batch rows per cluster
#define NCLUST  16
#define HROW    32        // floats per h row (32 batches)
#define HSKEW   8         // +8 floats per 64-row chunk (bank decorrelation)
#define HBUF_F  (UNITS * HROW + 4 * HSKEW)   // 8224 floats per h buffer
#define SLAB_F  (32 * 32)                    // 1024 floats = 4096 B
#define EXPECT_BYTES (CLUSTER * SLAB_F * 4)  // 32768 B per inbox phase

// z_x scratch: zx[t][b][c], c = unit*4 + gate, bias folded in. Two 1 GB halves.
__device__ float g_zxA[(size_t)512 * 512 * 1024];
__device__ float g_zxB[(size_t)512 * 512 * 1024];

// ---------- packed f32x2 helpers ----------
__device__ __forceinline__ unsigned long long dup2(float x) {
    unsigned long long r; uint32_t u = __float_as_uint(x);
    asm("mov.b64 %0, {%1, %1};" : "=l"(r) : "r"(u));
    return r;
}
__device__ __forceinline__ void fma2(unsigned long long& d,
                                     unsigned long long a,
                                     unsigned long long b) {
    asm("fma.rn.f32x2 %0, %1, %2, %0;" : "+l"(d) : "l"(a), "l"(b));
}
__device__ __forceinline__ float2 up2(unsigned long long v) {
    float2 r;
    asm("mov.b64 {%0, %1}, %2;" : "=f"(r.x), "=f"(r.y) : "l"(v));
    return r;
}
__device__ __forceinline__ unsigned long long xadd(unsigned long long v, int m) {
    uint32_t lo, hi;
    asm("mov.b64 {%0,%1}, %2;" : "=r"(lo), "=r"(hi) : "l"(v));
    lo = __shfl_xor_sync(0xffffffffu, lo, m);
    hi = __shfl_xor_sync(0xffffffffu, hi, m);
    unsigned long long o;
    asm("mov.b64 %0, {%1,%2};" : "=l"(o) : "r"(lo), "r"(hi));
    asm("add.rn.f32x2 %0, %0, %1;" : "+l"(v) : "l"(o));
    return v;
}
__device__ __forceinline__ float fsig(float x) {
    return __fdividef(1.0f, 1.0f + __expf(-x));
}
__device__ __forceinline__ float ftanh(float x) {
    return fmaf(2.0f, fsig(2.0f * x), -1.0f);
}
__device__ __forceinline__ void mbar_wait(uint32_t mbar, uint32_t parity) {
    uint32_t done;
    do {
        asm volatile(
            "{\n\t.reg .pred P;\n\t"
            "mbarrier.try_wait.parity.acquire.cluster.shared::cta.b64 P, [%1], %2, 0x989680;\n\t"
            "selp.b32 %0, 1, 0, P;\n\t}"
            : "=r"(done) : "r"(mbar), "r"(parity) : "memory");
    } while (!done);
}

// ============================================================================
// Kernel 1: zx = x @ W(perm) + bias(perm). 128x128 tile per 256-thr block,
// K staged in TWO 32-row chunks -> smem 33.8 KB -> 2 independent blocks/SM
// (4 warps/SMSP). Inner math identical to the proven R9 version.
// grid (8 col-tiles, 8 t-tiles, 512 b).
// ============================================================================
__global__ void __launch_bounds__(256)
zx_kernel(const float* __restrict__ x, const float* __restrict__ W,
          const float* __restrict__ bias)
{
    __shared__ float ws[32 * 132];    // 16896 B
    __shared__ float xs[32 * 132];    // 16896 B

    const int tid = threadIdx.x;
    const int cb  = blockIdx.x;
    const int tb  = blockIdx.y;
    const int b   = blockIdx.z;

    const int tx = tid & 15;
    const int ty = tid >> 4;

    unsigned long long acc[8][4];
    {
        unsigned long long bp[4];
        #pragma unroll
        for (int j = 0; j < 4; j++) {
            const int ca = cb * 128 + tx * 8 + 2 * j;
            const int cbn = ca + 1;
            uint32_t lo = __float_as_uint(bias[(ca  & 3) * UNITS + (ca  >> 2)]);
            uint32_t hi = __float_as_uint(bias[(cbn & 3) * UNITS + (cbn >> 2)]);
            unsigned long long r;
            asm("mov.b64 %0, {%1,%2};" : "=l"(r) : "r"(lo), "r"(hi));
            bp[j] = r;
        }
        #pragma unroll
        for (int i = 0; i < 8; i++)
            #pragma unroll
            for (int j = 0; j < 4; j++) acc[i][j] = bp[j];
    }

    const float* xb = x + ((size_t)b * TSTEPS + tb * 128) * FEAT;

    #pragma unroll
    for (int kc = 0; kc < 2; kc++) {          // two 32-row K chunks
        if (kc) __syncthreads();              // protect smem reuse
        // stage W chunk rows [kc*32, kc*32+32): ws[k][cc]
        for (int idx = tid; idx < 32 * 128; idx += 256) {
            const int k = idx >> 7, cc = idx & 127;
            const int c = cb * 128 + cc;
            ws[k * 132 + cc] = W[(size_t)(kc * 32 + k) * FOURU + (c & 3) * UNITS + (c >> 2)];
        }
        // stage x chunk transposed: xs[k][tt], k in [0,32)
        for (int idx = tid; idx < 128 * 8; idx += 256) {
            const int tt = idx >> 3, k4 = idx & 7;   // 8 float4 per row-chunk
            const float4 v = *(const float4*)(xb + (size_t)tt * FEAT + kc * 32 + k4 * 4);
            xs[(k4 * 4 + 0) * 132 + tt] = v.x;
            xs[(k4 * 4 + 1) * 132 + tt] = v.y;
            xs[(k4 * 4 + 2) * 132 + tt] = v.z;
            xs[(k4 * 4 + 3) * 132 + tt] = v.w;
        }
        __syncthreads();

        #pragma unroll 4
        for (int k = 0; k < 32; k++) {
            const float4 a0 = *(const float4*)(xs + k * 132 + ty * 8);
            const float4 a1 = *(const float4*)(xs + k * 132 + ty * 8 + 4);
            const ulonglong2 w0 = *(const ulonglong2*)(ws + k * 132 + tx * 8);
            const ulonglong2 w1 = *(const ulonglong2*)(ws + k * 132 + tx * 8 + 4);
            const unsigned long long wv[4] = { w0.x, w0.y, w1.x, w1.y };
            const unsigned long long ad[8] = { dup2(a0.x), dup2(a0.y), dup2(a0.z), dup2(a0.w),
                                               dup2(a1.x), dup2(a1.y), dup2(a1.z), dup2(a1.w) };
            #pragma unroll
            for (int i = 0; i < 8; i++)
                #pragma unroll
                for (int j = 0; j < 4; j++)
                    fma2(acc[i][j], ad[i], wv[j]);
        }
    }

    #pragma unroll
    for (int i = 0; i < 8; i++) {
        const int t = tb * 128 + ty * 8 + i;
        float* o = ((t < 512) ? g_zxA : g_zxB) +
                   ((size_t)(t & 511) * 512 + b) * FOURU + cb * 128 + tx * 8;
        const float2 p0 = up2(acc[i][0]), p1 = up2(acc[i][1]);
        const float2 p2 = up2(acc[i][2]), p3 = up2(acc[i][3]);
        *(float4*)(o)     = make_float4(p0.x, p0.y, p1.x, p1.y);
        *(float4*)(o + 4) = make_float4(p2.x, p2.y, p3.x, p3.y);
    }
}

// ============================================================================
// Kernel 2 (R11/R8, measured 13.08ms): recurrent LSTM. VERBATIM — protected.
// ============================================================================
extern "C" __global__ void __launch_bounds__(RTHREADS, 1) __cluster_dims__(CLUSTER, 1, 1)
lstm_kernel(const float* __restrict__ Uh, const float* __restrict__ dw,
            const float* __restrict__ db, float* __restrict__ out)
{
    extern __shared__ float smem[];
    float* Uc   = smem;                              // [256][128] 131072 B
    float* hb   = smem + UNITS * NCOLS;              // 2 x 8224 floats
    float* slab = hb + 2 * HBUF_F;                   // 2 x 1024 floats

    const int tid = threadIdx.x;
    uint32_t rank, cid;
    asm("mov.u32 %0, %%cluster_ctarank;" : "=r"(rank));
    asm("mov.u32 %0, %%clusterid.x;"     : "=r"(cid));

    uint32_t smem_u32;
    asm("{ .reg .u64 t0; cvta.to.shared.u64 t0, %1; cvt.u32.u64 %0, t0; }"
        : "=r"(smem_u32) : "l"(smem));
    const uint32_t hb_u32    = smem_u32 + UNITS * NCOLS * 4;
    const uint32_t slab_u32  = hb_u32 + 2 * HBUF_F * 4;
    const uint32_t inbox_u32 = slab_u32 + 2 * SLAB_F * 4;   // 2 mbarriers

    for (int idx = tid; idx < UNITS * NCOLS; idx += RTHREADS) {
        const int k = idx >> 7, c = idx & 127;
        const int gcol = (c & 3) * UNITS + (int)rank * 32 + (c >> 2);
        Uc[idx] = Uh[(size_t)k * FOURU + gcol];
    }
    for (int i = tid; i < 2 * HBUF_F; i += RTHREADS) hb[i] = 0.0f;
    if (tid == 0) {
        asm volatile("mbarrier.init.shared.b64 [%0], 1;" :: "r"(inbox_u32)     : "memory");
        asm volatile("mbarrier.init.shared.b64 [%0], 1;" :: "r"(inbox_u32 + 8) : "memory");
    }
    __syncthreads();
    asm volatile("barrier.cluster.arrive.aligned;" ::: "memory");
    asm volatile("barrier.cluster.wait.aligned;"   ::: "memory");

    const int wid  = tid >> 5, lane = tid & 31;
    const int ugq  = wid & 3;        // unit group (8 units)
    const int bq   = wid >> 2;       // batch group (8 batches), 0..3
    const int kq   = lane >> 3;      // K quarter
    const int u8   = lane & 7;
    const int unit = ugq * 8 + u8;   // local unit 0..31

    uint32_t dstb[CLUSTER], mbb[CLUSTER];
    {
        const uint32_t my_hoff = (uint32_t)(((int)rank * 1024 + ((int)rank >> 1) * HSKEW) * 4);
        #pragma unroll
        for (int r = 0; r < CLUSTER; r++) {
            asm("mapa.shared::cluster.u32 %0, %1, %2;" : "=r"(dstb[r]) : "r"(hb_u32 + my_hoff), "r"(r));
            asm("mapa.shared::cluster.u32 %0, %1, %2;" : "=r"(mbb[r])  : "r"(inbox_u32),        "r"(r));
        }
    }

    const int bloc = bq * 8 + kq * 2;                         // my 2 batches (local)
    const int b0   = (int)cid * BB + bloc;                    // global
    const int cb   = ((int)rank * 32 + unit) * 4;             // zx column base

    const float4* ucp = (const float4*)(Uc + unit * 4 + (kq * KQ) * NCOLS);
    const ulonglong2* apb = (const ulonglong2*)(hb + (kq * KQ) * HROW + kq * HSKEW + bq * 8);

    float cst[2] = {0.f, 0.f};

    float4 zc[2];
    #pragma unroll
    for (int j = 0; j < 2; j++)
        zc[j] = *(const float4*)(g_zxA + (size_t)(b0 + j) * FOURU + cb);

    for (int t = 0; t < TSTEPS; t++) {
        if (tid == 0) {
            asm volatile("mbarrier.arrive.expect_tx.shared.b64 _, [%0], %1;"
                :: "r"(inbox_u32 + (uint32_t)(((t + 1) & 1) * 8)),
                   "r"((uint32_t)EXPECT_BYTES) : "memory");
        }
        float4 zn[2];
        #pragma unroll
        for (int j = 0; j < 2; j++) zn[j] = zc[j];
        if (t < TSTEPS - 1) {
            const int tn = t + 1;
            const float* zp = ((tn < 512) ? g_zxA : g_zxB) +
                              ((size_t)(tn & 511) * 512 + b0) * FOURU + cb;
            #pragma unroll
            for (int j = 0; j < 2; j++) zn[j] = *(const float4*)(zp + (size_t)j * FOURU);
        }
        if (t > 0)
            mbar_wait(inbox_u32 + (uint32_t)((t & 1) * 8),
                      (uint32_t)(((t - 1) >> 1) & 1));

        unsigned long long acc[4][4];
        #pragma unroll
        for (int p = 0; p < 4; p++)
            #pragma unroll
            for (int g = 0; g < 4; g++) acc[p][g] = 0ull;

        const ulonglong2* ap = (const ulonglong2*)((const char*)apb +
                               (size_t)(t & 1) * (HBUF_F * 4));
        #pragma unroll 4
        for (int kk = 0; kk < KQ; kk++) {
            const float4 u4 = ucp[kk * 32];
            const unsigned long long ug[4] = { dup2(u4.x), dup2(u4.y),
                                               dup2(u4.z), dup2(u4.w) };
            const ulonglong2 a0 = ap[kk * 8 + 0];
            const ulonglong2 a1 = ap[kk * 8 + 1];
            const unsigned long long av[4] = { a0.x, a0.y, a1.x, a1.y };
            #pragma unroll
            for (int p = 0; p < 4; p++)
                #pragma unroll
                for (int g = 0; g < 4; g++)
                    fma2(acc[p][g], av[p], ug[g]);
        }

        #pragma unroll
        for (int p = 0; p < 4; p++)
            #pragma unroll
            for (int g = 0; g < 4; g++) {
                acc[p][g] = xadd(acc[p][g], 8);
                acc[p][g] = xadd(acc[p][g], 16);
            }

        const bool m1 = (kq >= 2), m0 = (kq & 1);
        unsigned long long zA[4];
        #pragma unroll
        for (int g = 0; g < 4; g++) {
            const unsigned long long s0 = m1 ? acc[2][g] : acc[0][g];
            const unsigned long long s1 = m1 ? acc[3][g] : acc[1][g];
            zA[g] = m0 ? s1 : s0;
        }

        const float2 zi = up2(zA[0]);
        const float2 zf = up2(zA[1]);
        const float2 zg = up2(zA[2]);
        const float2 zo = up2(zA[3]);
        float h0v, h1v;
        {
            const float ig = fsig(zi.x + zc[0].x), fg = fsig(zf.x + zc[0].y);
            const float gg = ftanh(zg.x + zc[0].z), og = fsig(zo.x + zc[0].w);
            cst[0] = fmaf(fg, cst[0], ig * gg);
            h0v    = og * ftanh(cst[0]);
        }
        {
            const float ig = fsig(zi.y + zc[1].x), fg = fsig(zf.y + zc[1].y);
            const float gg = ftanh(zg.y + zc[1].z), og = fsig(zo.y + zc[1].w);
            cst[1] = fmaf(fg, cst[1], ig * gg);
            h1v    = og * ftanh(cst[1]);
        }

        *(float2*)(slab + ((t + 1) & 1) * SLAB_F + unit * 32 + bloc) =
            make_float2(h0v, h1v);
        __syncthreads();
        if (tid == 0) {
            asm volatile("fence.proxy.async.shared::cta;" ::: "memory");
            const uint32_t src  = slab_u32 + (uint32_t)(((t + 1) & 1) * SLAB_F * 4);
            const uint32_t doff = (uint32_t)(((t + 1) & 1) * HBUF_F * 4);
            const uint32_t moff = (uint32_t)(((t + 1) & 1) * 8);
            #pragma unroll
            for (int r = 0; r < CLUSTER; r++) {
                asm volatile(
                    "cp.async.bulk.shared::cluster.shared::cta.mbarrier::complete_tx::bytes "
                    "[%0], [%1], %2, [%3];"
                    :: "r"(dstb[r] + doff), "r"(src), "r"((uint32_t)(SLAB_F * 4)),
                       "r"(mbb[r] + moff) : "memory");
            }
        }
        #pragma unroll
        for (int j = 0; j < 2; j++) zc[j] = zn[j];
    }

    mbar_wait(inbox_u32, (uint32_t)(((TSTEPS - 1) >> 1) & 1));
    asm volatile("barrier.cluster.arrive.aligned;" ::: "memory");

    {
        const int bl = (int)rank * 4 + (wid & 3);     // local batch 0..31
        float s = 0.0f;
        for (int u = lane; u < UNITS; u += 32)
            s += hb[u * HROW + (u >> 6) * HSKEW + bl] * dw[u];
        #pragma unroll
        for (int o = 16; o > 0; o >>= 1)
            s += __shfl_xor_sync(0xffffffffu, s, o);
        const float val = fsig(s + db[0]);
        float* op = out + ((size_t)cid * BB + bl) * TSTEPS + (wid >> 2) * 256;
        for (int i = lane; i < 256; i += 32)
            op[i] = val;
    }
    asm volatile("barrier.cluster.wait.aligned;" ::: "memory");
}

extern "C" void kernel_launch(void* const* d_in, const int* in_sizes, int n_in,
                              void* d_out, int out_size)
{
    const float* x  = (const float*)d_in[0];
    const float* W  = (const float*)d_in[1];
    const float* Uh = (const float*)d_in[2];
    const float* b  = (const float*)d_in[3];
    const float* dw = (const float*)d_in[4];
    const float* db = (const float*)d_in[5];
    float* out = (float*)d_out;

    zx_kernel<<<dim3(8, 8, 512), 256>>>(x, W, b);

    const size_t rsm = (size_t)(UNITS * NCOLS + 2 * HBUF_F + 2 * SLAB_F) * sizeof(float) + 32;
    cudaFuncSetAttribute(lstm_kernel,
                         cudaFuncAttributeMaxDynamicSharedMemorySize, (int)rsm);
    lstm_kernel<<<NCLUST * CLUSTER, RTHREADS, rsm>>>(Uh, dw, db, out);
}

// round 16
// speedup vs baseline: 1.0350x; 1.0129x over previous
#include <cuda_runtime.h>
#include <cstdint>

#define TSTEPS  1024
#define FEAT    64
#define UNITS   256
#define FOURU   1024
#define KQ      64        // K rows per k-quarter (K = 256, h only)
#define NCOLS   128       // gate-columns per CTA: 32 units x 4 gates
#define CLUSTER 8
#define RTHREADS 512
#define BB      32        // batch rows per cluster
#define NCLUST  16
#define HROW    32        // floats per h row (32 batches)
#define HSKEW   8         // +8 floats per 64-row chunk (bank decorrelation)
#define HBUF_F  (UNITS * HROW + 4 * HSKEW)   // 8224 floats per h buffer
#define SLAB_F  (32 * 32)                    // 1024 floats = 4096 B
#define EXPECT_BYTES (CLUSTER * SLAB_F * 4)  // 32768 B per inbox phase

// z_x scratch: zx[t][b][c], c = unit*4 + gate, bias folded in. Two 1 GB halves.
__device__ float g_zxA[(size_t)512 * 512 * 1024];
__device__ float g_zxB[(size_t)512 * 512 * 1024];

// ---------- packed f32x2 helpers ----------
__device__ __forceinline__ unsigned long long dup2(float x) {
    unsigned long long r; uint32_t u = __float_as_uint(x);
    asm("mov.b64 %0, {%1, %1};" : "=l"(r) : "r"(u));
    return r;
}
__device__ __forceinline__ void fma2(unsigned long long& d,
                                     unsigned long long a,
                                     unsigned long long b) {
    asm("fma.rn.f32x2 %0, %1, %2, %0;" : "+l"(d) : "l"(a), "l"(b));
}
__device__ __forceinline__ float2 up2(unsigned long long v) {
    float2 r;
    asm("mov.b64 {%0, %1}, %2;" : "=f"(r.x), "=f"(r.y) : "l"(v));
    return r;
}
__device__ __forceinline__ unsigned long long xadd(unsigned long long v, int m) {
    uint32_t lo, hi;
    asm("mov.b64 {%0,%1}, %2;" : "=r"(lo), "=r"(hi) : "l"(v));
    lo = __shfl_xor_sync(0xffffffffu, lo, m);
    hi = __shfl_xor_sync(0xffffffffu, hi, m);
    unsigned long long o;
    asm("mov.b64 %0, {%1,%2};" : "=l"(o) : "r"(lo), "r"(hi));
    asm("add.rn.f32x2 %0, %0, %1;" : "+l"(v) : "l"(o));
    return v;
}
__device__ __forceinline__ float fsig(float x) {
    return __fdividef(1.0f, 1.0f + __expf(-x));
}
__device__ __forceinline__ float ftanh(float x) {
    return fmaf(2.0f, fsig(2.0f * x), -1.0f);
}
__device__ __forceinline__ void mbar_wait(uint32_t mbar, uint32_t parity) {
    uint32_t done;
    do {
        asm volatile(
            "{\n\t.reg .pred P;\n\t"
            "mbarrier.try_wait.parity.acquire.cluster.shared::cta.b64 P, [%1], %2, 0x989680;\n\t"
            "selp.b32 %0, 1, 0, P;\n\t}"
            : "=r"(done) : "r"(mbar), "r"(parity) : "memory");
    } while (!done);
}

// ============================================================================
// Kernel 1: zx = x @ W(perm) + bias(perm). R9-exact 128x128 fp32 tile GEMM
// (measured 1.75ms) with ONE change: __launch_bounds__(256, 2) caps regs at
// 128 so 2 blocks co-reside per SM (4 warps/SMSP instead of 2).
// grid (8 col-tiles, 8 t-tiles, 512 b).
// ============================================================================
__global__ void __launch_bounds__(256, 2)
zx_kernel(const float* __restrict__ x, const float* __restrict__ W,
          const float* __restrict__ bias)
{
    __shared__ float ws[64 * 132];
    __shared__ float xs[64 * 132];

    const int tid = threadIdx.x;
    const int cb  = blockIdx.x;
    const int tb  = blockIdx.y;
    const int b   = blockIdx.z;

    for (int idx = tid; idx < 64 * 128; idx += 256) {
        const int k = idx >> 7, cc = idx & 127;
        const int c = cb * 128 + cc;
        ws[k * 132 + cc] = W[(size_t)k * FOURU + (c & 3) * UNITS + (c >> 2)];
    }
    {
        const float* xb = x + ((size_t)b * TSTEPS + tb * 128) * FEAT;
        for (int idx = tid; idx < 128 * 16; idx += 256) {
            const int tt = idx >> 4, k4 = idx & 15;
            const float4 v = *(const float4*)(xb + (size_t)tt * FEAT + k4 * 4);
            xs[(k4 * 4 + 0) * 132 + tt] = v.x;
            xs[(k4 * 4 + 1) * 132 + tt] = v.y;
            xs[(k4 * 4 + 2) * 132 + tt] = v.z;
            xs[(k4 * 4 + 3) * 132 + tt] = v.w;
        }
    }
    __syncthreads();

    const int tx = tid & 15;
    const int ty = tid >> 4;

    unsigned long long acc[8][4];
    {
        unsigned long long bp[4];
        #pragma unroll
        for (int j = 0; j < 4; j++) {
            const int ca = cb * 128 + tx * 8 + 2 * j;
            const int cbn = ca + 1;
            uint32_t lo = __float_as_uint(bias[(ca  & 3) * UNITS + (ca  >> 2)]);
            uint32_t hi = __float_as_uint(bias[(cbn & 3) * UNITS + (cbn >> 2)]);
            unsigned long long r;
            asm("mov.b64 %0, {%1,%2};" : "=l"(r) : "r"(lo), "r"(hi));
            bp[j] = r;
        }
        #pragma unroll
        for (int i = 0; i < 8; i++)
            #pragma unroll
            for (int j = 0; j < 4; j++) acc[i][j] = bp[j];
    }

    #pragma unroll 4
    for (int k = 0; k < 64; k++) {
        const float4 a0 = *(const float4*)(xs + k * 132 + ty * 8);
        const float4 a1 = *(const float4*)(xs + k * 132 + ty * 8 + 4);
        const ulonglong2 w0 = *(const ulonglong2*)(ws + k * 132 + tx * 8);
        const ulonglong2 w1 = *(const ulonglong2*)(ws + k * 132 + tx * 8 + 4);
        const unsigned long long wv[4] = { w0.x, w0.y, w1.x, w1.y };
        const unsigned long long ad[8] = { dup2(a0.x), dup2(a0.y), dup2(a0.z), dup2(a0.w),
                                           dup2(a1.x), dup2(a1.y), dup2(a1.z), dup2(a1.w) };
        #pragma unroll
        for (int i = 0; i < 8; i++)
            #pragma unroll
            for (int j = 0; j < 4; j++)
                fma2(acc[i][j], ad[i], wv[j]);
    }

    #pragma unroll
    for (int i = 0; i < 8; i++) {
        const int t = tb * 128 + ty * 8 + i;
        float* o = ((t < 512) ? g_zxA : g_zxB) +
                   ((size_t)(t & 511) * 512 + b) * FOURU + cb * 128 + tx * 8;
        const float2 p0 = up2(acc[i][0]), p1 = up2(acc[i][1]);
        const float2 p2 = up2(acc[i][2]), p3 = up2(acc[i][3]);
        *(float4*)(o)     = make_float4(p0.x, p0.y, p1.x, p1.y);
        *(float4*)(o + 4) = make_float4(p2.x, p2.y, p3.x, p3.y);
    }
}

// ============================================================================
// Kernel 2 (R11/R8, measured 13.08ms): recurrent LSTM. VERBATIM — protected.
// 16 clusters x 8 CTAs x 512 thr. Uh slice in SMEM; thread = 8 batches x
// 4 gates over K-quarter; butterfly reduce over kq lanes; h exchanged via
// slab + 8 cp.async.bulk per CTA/step into double-buffered bank-skewed h
// buffers (single inbox mbarrier per buffer). Epilogue: softmax over the
// size-1 axis == 1 -> out[b,:] = sigmoid(h_T . dw + db).
// ============================================================================
extern "C" __global__ void __launch_bounds__(RTHREADS, 1) __cluster_dims__(CLUSTER, 1, 1)
lstm_kernel(const float* __restrict__ Uh, const float* __restrict__ dw,
            const float* __restrict__ db, float* __restrict__ out)
{
    extern __shared__ float smem[];
    float* Uc   = smem;                              // [256][128] 131072 B
    float* hb   = smem + UNITS * NCOLS;              // 2 x 8224 floats
    float* slab = hb + 2 * HBUF_F;                   // 2 x 1024 floats

    const int tid = threadIdx.x;
    uint32_t rank, cid;
    asm("mov.u32 %0, %%cluster_ctarank;" : "=r"(rank));
    asm("mov.u32 %0, %%clusterid.x;"     : "=r"(cid));

    uint32_t smem_u32;
    asm("{ .reg .u64 t0; cvta.to.shared.u64 t0, %1; cvt.u32.u64 %0, t0; }"
        : "=r"(smem_u32) : "l"(smem));
    const uint32_t hb_u32    = smem_u32 + UNITS * NCOLS * 4;
    const uint32_t slab_u32  = hb_u32 + 2 * HBUF_F * 4;
    const uint32_t inbox_u32 = slab_u32 + 2 * SLAB_F * 4;   // 2 mbarriers

    for (int idx = tid; idx < UNITS * NCOLS; idx += RTHREADS) {
        const int k = idx >> 7, c = idx & 127;
        const int gcol = (c & 3) * UNITS + (int)rank * 32 + (c >> 2);
        Uc[idx] = Uh[(size_t)k * FOURU + gcol];
    }
    for (int i = tid; i < 2 * HBUF_F; i += RTHREADS) hb[i] = 0.0f;
    if (tid == 0) {
        asm volatile("mbarrier.init.shared.b64 [%0], 1;" :: "r"(inbox_u32)     : "memory");
        asm volatile("mbarrier.init.shared.b64 [%0], 1;" :: "r"(inbox_u32 + 8) : "memory");
    }
    __syncthreads();
    asm volatile("barrier.cluster.arrive.aligned;" ::: "memory");
    asm volatile("barrier.cluster.wait.aligned;"   ::: "memory");

    const int wid  = tid >> 5, lane = tid & 31;
    const int ugq  = wid & 3;        // unit group (8 units)
    const int bq   = wid >> 2;       // batch group (8 batches), 0..3
    const int kq   = lane >> 3;      // K quarter
    const int u8   = lane & 7;
    const int unit = ugq * 8 + u8;   // local unit 0..31

    uint32_t dstb[CLUSTER], mbb[CLUSTER];
    {
        const uint32_t my_hoff = (uint32_t)(((int)rank * 1024 + ((int)rank >> 1) * HSKEW) * 4);
        #pragma unroll
        for (int r = 0; r < CLUSTER; r++) {
            asm("mapa.shared::cluster.u32 %0, %1, %2;" : "=r"(dstb[r]) : "r"(hb_u32 + my_hoff), "r"(r));
            asm("mapa.shared::cluster.u32 %0, %1, %2;" : "=r"(mbb[r])  : "r"(inbox_u32),        "r"(r));
        }
    }

    const int bloc = bq * 8 + kq * 2;                         // my 2 batches (local)
    const int b0   = (int)cid * BB + bloc;                    // global
    const int cb   = ((int)rank * 32 + unit) * 4;             // zx column base

    const float4* ucp = (const float4*)(Uc + unit * 4 + (kq * KQ) * NCOLS);
    const ulonglong2* apb = (const ulonglong2*)(hb + (kq * KQ) * HROW + kq * HSKEW + bq * 8);

    float cst[2] = {0.f, 0.f};

    float4 zc[2];
    #pragma unroll
    for (int j = 0; j < 2; j++)
        zc[j] = *(const float4*)(g_zxA + (size_t)(b0 + j) * FOURU + cb);

    for (int t = 0; t < TSTEPS; t++) {
        if (tid == 0) {
            asm volatile("mbarrier.arrive.expect_tx.shared.b64 _, [%0], %1;"
                :: "r"(inbox_u32 + (uint32_t)(((t + 1) & 1) * 8)),
                   "r"((uint32_t)EXPECT_BYTES) : "memory");
        }
        float4 zn[2];
        #pragma unroll
        for (int j = 0; j < 2; j++) zn[j] = zc[j];
        if (t < TSTEPS - 1) {
            const int tn = t + 1;
            const float* zp = ((tn < 512) ? g_zxA : g_zxB) +
                              ((size_t)(tn & 511) * 512 + b0) * FOURU + cb;
            #pragma unroll
            for (int j = 0; j < 2; j++) zn[j] = *(const float4*)(zp + (size_t)j * FOURU);
        }
        if (t > 0)
            mbar_wait(inbox_u32 + (uint32_t)((t & 1) * 8),
                      (uint32_t)(((t - 1) >> 1) & 1));

        unsigned long long acc[4][4];
        #pragma unroll
        for (int p = 0; p < 4; p++)
            #pragma unroll
            for (int g = 0; g < 4; g++) acc[p][g] = 0ull;

        const ulonglong2* ap = (const ulonglong2*)((const char*)apb +
                               (size_t)(t & 1) * (HBUF_F * 4));
        #pragma unroll 4
        for (int kk = 0; kk < KQ; kk++) {
            const float4 u4 = ucp[kk * 32];
            const unsigned long long ug[4] = { dup2(u4.x), dup2(u4.y),
                                               dup2(u4.z), dup2(u4.w) };
            const ulonglong2 a0 = ap[kk * 8 + 0];
            const ulonglong2 a1 = ap[kk * 8 + 1];
            const unsigned long long av[4] = { a0.x, a0.y, a1.x, a1.y };
            #pragma unroll
            for (int p = 0; p < 4; p++)
                #pragma unroll
                for (int g = 0; g < 4; g++)
                    fma2(acc[p][g], av[p], ug[g]);
        }

        #pragma unroll
        for (int p = 0; p < 4; p++)
            #pragma unroll
            for (int g = 0; g < 4; g++) {
                acc[p][g] = xadd(acc[p][g], 8);
                acc[p][g] = xadd(acc[p][g], 16);
            }

        const bool m1 = (kq >= 2), m0 = (kq & 1);
        unsigned long long zA[4];
        #pragma unroll
        for (int g = 0; g < 4; g++) {
            const unsigned long long s0 = m1 ? acc[2][g] : acc[0][g];
            const unsigned long long s1 = m1 ? acc[3][g] : acc[1][g];
            zA[g] = m0 ? s1 : s0;
        }

        const float2 zi = up2(zA[0]);
        const float2 zf = up2(zA[1]);
        const float2 zg = up2(zA[2]);
        const float2 zo = up2(zA[3]);
        float h0v, h1v;
        {
            const float ig = fsig(zi.x + zc[0].x), fg = fsig(zf.x + zc[0].y);
            const float gg = ftanh(zg.x + zc[0].z), og = fsig(zo.x + zc[0].w);
            cst[0] = fmaf(fg, cst[0], ig * gg);
            h0v    = og * ftanh(cst[0]);
        }
        {
            const float ig = fsig(zi.y + zc[1].x), fg = fsig(zf.y + zc[1].y);
            const float gg = ftanh(zg.y + zc[1].z), og = fsig(zo.y + zc[1].w);
            cst[1] = fmaf(fg, cst[1], ig * gg);
            h1v    = og * ftanh(cst[1]);
        }

        *(float2*)(slab + ((t + 1) & 1) * SLAB_F + unit * 32 + bloc) =
            make_float2(h0v, h1v);
        __syncthreads();
        if (tid == 0) {
            asm volatile("fence.proxy.async.shared::cta;" ::: "memory");
            const uint32_t src  = slab_u32 + (uint32_t)(((t + 1) & 1) * SLAB_F * 4);
            const uint32_t doff = (uint32_t)(((t + 1) & 1) * HBUF_F * 4);
            const uint32_t moff = (uint32_t)(((t + 1) & 1) * 8);
            #pragma unroll
            for (int r = 0; r < CLUSTER; r++) {
                asm volatile(
                    "cp.async.bulk.shared::cluster.shared::cta.mbarrier::complete_tx::bytes "
                    "[%0], [%1], %2, [%3];"
                    :: "r"(dstb[r] + doff), "r"(src), "r"((uint32_t)(SLAB_F * 4)),
                       "r"(mbb[r] + moff) : "memory");
            }
        }
        #pragma unroll
        for (int j = 0; j < 2; j++) zc[j] = zn[j];
    }

    mbar_wait(inbox_u32, (uint32_t)(((TSTEPS - 1) >> 1) & 1));
    asm volatile("barrier.cluster.arrive.aligned;" ::: "memory");

    {
        const int bl = (int)rank * 4 + (wid & 3);     // local batch 0..31
        float s = 0.0f;
        for (int u = lane; u < UNITS; u += 32)
            s += hb[u * HROW + (u >> 6) * HSKEW + bl] * dw[u];
        #pragma unroll
        for (int o = 16; o > 0; o >>= 1)
            s += __shfl_xor_sync(0xffffffffu, s, o);
        const float val = fsig(s + db[0]);
        float* op = out + ((size_t)cid * BB + bl) * TSTEPS + (wid >> 2) * 256;
        for (int i = lane; i < 256; i += 32)
            op[i] = val;
    }
    asm volatile("barrier.cluster.wait.aligned;" ::: "memory");
}

extern "C" void kernel_launch(void* const* d_in, const int* in_sizes, int n_in,
                              void* d_out, int out_size)
{
    const float* x  = (const float*)d_in[0];
    const float* W  = (const float*)d_in[1];
    const float* Uh = (const float*)d_in[2];
    const float* b  = (const float*)d_in[3];
    const float* dw = (const float*)d_in[4];
    const float* db = (const float*)d_in[5];
    float* out = (float*)d_out;

    zx_kernel<<<dim3(8, 8, 512), 256>>>(x, W, b);

    const size_t rsm = (size_t)(UNITS * NCOLS + 2 * HBUF_F + 2 * SLAB_F) * sizeof(float) + 32;
    cudaFuncSetAttribute(lstm_kernel,
                         cudaFuncAttributeMaxDynamicSharedMemorySize, (int)rsm);
    lstm_kernel<<<NCLUST * CLUSTER, RTHREADS, rsm>>>(Uh, dw, db, out);
}

// round 17
// speedup vs baseline: 1.1592x; 1.1200x over previous
#include <cuda_runtime.h>
#include <cstdint>

#define TSTEPS  1024
#define FEAT    64
#define UNITS   256
#define FOURU   1024
#define KQ      64        // K rows per k-quarter (K = 256, h only)
#define NCOLS   128       // gate-columns per CTA: 32 units x 4 gates
#define CLUSTER 8
#define RTHREADS 512
#define BB      32        // batch rows per cluster
#define NCLUST  16
#define HROW    32        // floats per h row (32 batches)
#define HSKEW   8         // +8 floats per 64-row chunk (bank decorrelation)
#define HBUF_F  (UNITS * HROW + 4 * HSKEW)   // 8224 floats per h buffer
#define SLAB_F  (32 * 32)                    // 1024 floats = 4096 B
#define EXPECT_BYTES (CLUSTER * SLAB_F * 4)  // 32768 B per inbox phase
#define NTILES  8                            // 128-t tiles
#define TILE_BLOCKS 4096                     // zx blocks per tile (8 cb x 512 b)

// z_x scratch: zx[t][b][c], c = unit*4 + gate, bias folded in. Two 1 GB halves.
__device__ float g_zxA[(size_t)512 * 512 * 1024];
__device__ float g_zxB[(size_t)512 * 512 * 1024];
__device__ int   g_done[NTILES];             // zx blocks completed per t-tile

// ---------- packed f32x2 helpers ----------
__device__ __forceinline__ unsigned long long dup2(float x) {
    unsigned long long r; uint32_t u = __float_as_uint(x);
    asm("mov.b64 %0, {%1, %1};" : "=l"(r) : "r"(u));
    return r;
}
__device__ __forceinline__ void fma2(unsigned long long& d,
                                     unsigned long long a,
                                     unsigned long long b) {
    asm("fma.rn.f32x2 %0, %1, %2, %0;" : "+l"(d) : "l"(a), "l"(b));
}
__device__ __forceinline__ float2 up2(unsigned long long v) {
    float2 r;
    asm("mov.b64 {%0, %1}, %2;" : "=f"(r.x), "=f"(r.y) : "l"(v));
    return r;
}
__device__ __forceinline__ unsigned long long xadd(unsigned long long v, int m) {
    uint32_t lo, hi;
    asm("mov.b64 {%0,%1}, %2;" : "=r"(lo), "=r"(hi) : "l"(v));
    lo = __shfl_xor_sync(0xffffffffu, lo, m);
    hi = __shfl_xor_sync(0xffffffffu, hi, m);
    unsigned long long o;
    asm("mov.b64 %0, {%1,%2};" : "=l"(o) : "r"(lo), "r"(hi));
    asm("add.rn.f32x2 %0, %0, %1;" : "+l"(v) : "l"(o));
    return v;
}
__device__ __forceinline__ float fsig(float x) {
    return __fdividef(1.0f, 1.0f + __expf(-x));
}
__device__ __forceinline__ float ftanh(float x) {
    return fmaf(2.0f, fsig(2.0f * x), -1.0f);
}
__device__ __forceinline__ void mbar_wait(uint32_t mbar, uint32_t parity) {
    uint32_t done;
    do {
        asm volatile(
            "{\n\t.reg .pred P;\n\t"
            "mbarrier.try_wait.parity.acquire.cluster.shared::cta.b64 P, [%1], %2, 0x989680;\n\t"
            "selp.b32 %0, 1, 0, P;\n\t}"
            : "=r"(done) : "r"(mbar), "r"(parity) : "memory");
    } while (!done);
}
// consumer-side: spin until tile produced (tid 0 only), device-scope acquire
__device__ __forceinline__ void wait_tile(int tile) {
    int v;
    do {
        asm volatile("ld.global.cv.s32 %0, [%1];" : "=r"(v)
                     : "l"(&g_done[tile]) : "memory");
    } while (v < TILE_BLOCKS);
    __threadfence();
}

// ============================================================================
// Kernel 0: reset per-tile progress flags (runs first, every execution).
// ============================================================================
__global__ void reset_kernel() {
    if (threadIdx.x < NTILES) g_done[threadIdx.x] = 0;
}

// ============================================================================
// Kernel 1: zx = x @ W(perm) + bias(perm). R9-exact math; grid remapped to
// (cb, b, tile) so tiles complete in order; per-tile completion flag.
// tb_off selects head (tile 0) vs tail (tiles 1..7).
// ============================================================================
__global__ void __launch_bounds__(256)
zx_kernel(const float* __restrict__ x, const float* __restrict__ W,
          const float* __restrict__ bias, int tb_off)
{
    __shared__ float ws[64 * 132];
    __shared__ float xs[64 * 132];

    const int tid = threadIdx.x;
    const int cb  = blockIdx.x;
    const int b   = blockIdx.y;
    const int tb  = blockIdx.z + tb_off;

    for (int idx = tid; idx < 64 * 128; idx += 256) {
        const int k = idx >> 7, cc = idx & 127;
        const int c = cb * 128 + cc;
        ws[k * 132 + cc] = W[(size_t)k * FOURU + (c & 3) * UNITS + (c >> 2)];
    }
    {
        const float* xb = x + ((size_t)b * TSTEPS + tb * 128) * FEAT;
        for (int idx = tid; idx < 128 * 16; idx += 256) {
            const int tt = idx >> 4, k4 = idx & 15;
            const float4 v = *(const float4*)(xb + (size_t)tt * FEAT + k4 * 4);
            xs[(k4 * 4 + 0) * 132 + tt] = v.x;
            xs[(k4 * 4 + 1) * 132 + tt] = v.y;
            xs[(k4 * 4 + 2) * 132 + tt] = v.z;
            xs[(k4 * 4 + 3) * 132 + tt] = v.w;
        }
    }
    __syncthreads();

    const int tx = tid & 15;
    const int ty = tid >> 4;

    unsigned long long acc[8][4];
    {
        unsigned long long bp[4];
        #pragma unroll
        for (int j = 0; j < 4; j++) {
            const int ca = cb * 128 + tx * 8 + 2 * j;
            const int cbn = ca + 1;
            uint32_t lo = __float_as_uint(bias[(ca  & 3) * UNITS + (ca  >> 2)]);
            uint32_t hi = __float_as_uint(bias[(cbn & 3) * UNITS + (cbn >> 2)]);
            unsigned long long r;
            asm("mov.b64 %0, {%1,%2};" : "=l"(r) : "r"(lo), "r"(hi));
            bp[j] = r;
        }
        #pragma unroll
        for (int i = 0; i < 8; i++)
            #pragma unroll
            for (int j = 0; j < 4; j++) acc[i][j] = bp[j];
    }

    #pragma unroll 4
    for (int k = 0; k < 64; k++) {
        const float4 a0 = *(const float4*)(xs + k * 132 + ty * 8);
        const float4 a1 = *(const float4*)(xs + k * 132 + ty * 8 + 4);
        const ulonglong2 w0 = *(const ulonglong2*)(ws + k * 132 + tx * 8);
        const ulonglong2 w1 = *(const ulonglong2*)(ws + k * 132 + tx * 8 + 4);
        const unsigned long long wv[4] = { w0.x, w0.y, w1.x, w1.y };
        const unsigned long long ad[8] = { dup2(a0.x), dup2(a0.y), dup2(a0.z), dup2(a0.w),
                                           dup2(a1.x), dup2(a1.y), dup2(a1.z), dup2(a1.w) };
        #pragma unroll
        for (int i = 0; i < 8; i++)
            #pragma unroll
            for (int j = 0; j < 4; j++)
                fma2(acc[i][j], ad[i], wv[j]);
    }

    #pragma unroll
    for (int i = 0; i < 8; i++) {
        const int t = tb * 128 + ty * 8 + i;
        float* o = ((t < 512) ? g_zxA : g_zxB) +
                   ((size_t)(t & 511) * 512 + b) * FOURU + cb * 128 + tx * 8;
        const float2 p0 = up2(acc[i][0]), p1 = up2(acc[i][1]);
        const float2 p2 = up2(acc[i][2]), p3 = up2(acc[i][3]);
        *(float4*)(o)     = make_float4(p0.x, p0.y, p1.x, p1.y);
        *(float4*)(o + 4) = make_float4(p2.x, p2.y, p3.x, p3.y);
    }

    // release: all stores device-visible before flagging tile progress
    __threadfence();
    __syncthreads();
    if (tid == 0) atomicAdd(&g_done[tb], 1);
}

// ============================================================================
// Kernel 2 (R11/R8, measured 13.08ms): recurrent LSTM + 8 gated tile-waits.
// Math, exchange protocol, epilogue all VERBATIM.
// ============================================================================
extern "C" __global__ void __launch_bounds__(RTHREADS, 1) __cluster_dims__(CLUSTER, 1, 1)
lstm_kernel(const float* __restrict__ Uh, const float* __restrict__ dw,
            const float* __restrict__ db, float* __restrict__ out)
{
    extern __shared__ float smem[];
    float* Uc   = smem;                              // [256][128] 131072 B
    float* hb   = smem + UNITS * NCOLS;              // 2 x 8224 floats
    float* slab = hb + 2 * HBUF_F;                   // 2 x 1024 floats

    const int tid = threadIdx.x;
    uint32_t rank, cid;
    asm("mov.u32 %0, %%cluster_ctarank;" : "=r"(rank));
    asm("mov.u32 %0, %%clusterid.x;"     : "=r"(cid));

    uint32_t smem_u32;
    asm("{ .reg .u64 t0; cvta.to.shared.u64 t0, %1; cvt.u32.u64 %0, t0; }"
        : "=r"(smem_u32) : "l"(smem));
    const uint32_t hb_u32    = smem_u32 + UNITS * NCOLS * 4;
    const uint32_t slab_u32  = hb_u32 + 2 * HBUF_F * 4;
    const uint32_t inbox_u32 = slab_u32 + 2 * SLAB_F * 4;   // 2 mbarriers

    for (int idx = tid; idx < UNITS * NCOLS; idx += RTHREADS) {
        const int k = idx >> 7, c = idx & 127;
        const int gcol = (c & 3) * UNITS + (int)rank * 32 + (c >> 2);
        Uc[idx] = Uh[(size_t)k * FOURU + gcol];
    }
    for (int i = tid; i < 2 * HBUF_F; i += RTHREADS) hb[i] = 0.0f;
    if (tid == 0) {
        asm volatile("mbarrier.init.shared.b64 [%0], 1;" :: "r"(inbox_u32)     : "memory");
        asm volatile("mbarrier.init.shared.b64 [%0], 1;" :: "r"(inbox_u32 + 8) : "memory");
    }
    __syncthreads();
    asm volatile("barrier.cluster.arrive.aligned;" ::: "memory");
    asm volatile("barrier.cluster.wait.aligned;"   ::: "memory");

    const int wid  = tid >> 5, lane = tid & 31;
    const int ugq  = wid & 3;        // unit group (8 units)
    const int bq   = wid >> 2;       // batch group (8 batches), 0..3
    const int kq   = lane >> 3;      // K quarter
    const int u8   = lane & 7;
    const int unit = ugq * 8 + u8;   // local unit 0..31

    uint32_t dstb[CLUSTER], mbb[CLUSTER];
    {
        const uint32_t my_hoff = (uint32_t)(((int)rank * 1024 + ((int)rank >> 1) * HSKEW) * 4);
        #pragma unroll
        for (int r = 0; r < CLUSTER; r++) {
            asm("mapa.shared::cluster.u32 %0, %1, %2;" : "=r"(dstb[r]) : "r"(hb_u32 + my_hoff), "r"(r));
            asm("mapa.shared::cluster.u32 %0, %1, %2;" : "=r"(mbb[r])  : "r"(inbox_u32),        "r"(r));
        }
    }

    const int bloc = bq * 8 + kq * 2;                         // my 2 batches (local)
    const int b0   = (int)cid * BB + bloc;                    // global
    const int cb   = ((int)rank * 32 + unit) * 4;             // zx column base

    const float4* ucp = (const float4*)(Uc + unit * 4 + (kq * KQ) * NCOLS);
    const ulonglong2* apb = (const ulonglong2*)(hb + (kq * KQ) * HROW + kq * HSKEW + bq * 8);

    float cst[2] = {0.f, 0.f};

    // wait for zx tile 0, then preload zx(t=0)
    if (tid == 0) wait_tile(0);
    __syncthreads();
    float4 zc[2];
    #pragma unroll
    for (int j = 0; j < 2; j++)
        zc[j] = *(const float4*)(g_zxA + (size_t)(b0 + j) * FOURU + cb);

    for (int t = 0; t < TSTEPS; t++) {
        if (tid == 0) {
            asm volatile("mbarrier.arrive.expect_tx.shared.b64 _, [%0], %1;"
                :: "r"(inbox_u32 + (uint32_t)(((t + 1) & 1) * 8)),
                   "r"((uint32_t)EXPECT_BYTES) : "memory");
        }
        float4 zn[2];
        #pragma unroll
        for (int j = 0; j < 2; j++) zn[j] = zc[j];
        if (t < TSTEPS - 1) {
            const int tn = t + 1;
            if ((tn & 127) == 0) {            // entering a new 128-t zx tile
                if (tid == 0) wait_tile(tn >> 7);
                __syncthreads();
            }
            const float* zp = ((tn < 512) ? g_zxA : g_zxB) +
                              ((size_t)(tn & 511) * 512 + b0) * FOURU + cb;
            #pragma unroll
            for (int j = 0; j < 2; j++) zn[j] = *(const float4*)(zp + (size_t)j * FOURU);
        }
        if (t > 0)
            mbar_wait(inbox_u32 + (uint32_t)((t & 1) * 8),
                      (uint32_t)(((t - 1) >> 1) & 1));

        unsigned long long acc[4][4];
        #pragma unroll
        for (int p = 0; p < 4; p++)
            #pragma unroll
            for (int g = 0; g < 4; g++) acc[p][g] = 0ull;

        const ulonglong2* ap = (const ulonglong2*)((const char*)apb +
                               (size_t)(t & 1) * (HBUF_F * 4));
        #pragma unroll 4
        for (int kk = 0; kk < KQ; kk++) {
            const float4 u4 = ucp[kk * 32];
            const unsigned long long ug[4] = { dup2(u4.x), dup2(u4.y),
                                               dup2(u4.z), dup2(u4.w) };
            const ulonglong2 a0 = ap[kk * 8 + 0];
            const ulonglong2 a1 = ap[kk * 8 + 1];
            const unsigned long long av[4] = { a0.x, a0.y, a1.x, a1.y };
            #pragma unroll
            for (int p = 0; p < 4; p++)
                #pragma unroll
                for (int g = 0; g < 4; g++)
                    fma2(acc[p][g], av[p], ug[g]);
        }

        #pragma unroll
        for (int p = 0; p < 4; p++)
            #pragma unroll
            for (int g = 0; g < 4; g++) {
                acc[p][g] = xadd(acc[p][g], 8);
                acc[p][g] = xadd(acc[p][g], 16);
            }

        const bool m1 = (kq >= 2), m0 = (kq & 1);
        unsigned long long zA[4];
        #pragma unroll
        for (int g = 0; g < 4; g++) {
            const unsigned long long s0 = m1 ? acc[2][g] : acc[0][g];
            const unsigned long long s1 = m1 ? acc[3][g] : acc[1][g];
            zA[g] = m0 ? s1 : s0;
        }

        const float2 zi = up2(zA[0]);
        const float2 zf = up2(zA[1]);
        const float2 zg = up2(zA[2]);
        const float2 zo = up2(zA[3]);
        float h0v, h1v;
        {
            const float ig = fsig(zi.x + zc[0].x), fg = fsig(zf.x + zc[0].y);
            const float gg = ftanh(zg.x + zc[0].z), og = fsig(zo.x + zc[0].w);
            cst[0] = fmaf(fg, cst[0], ig * gg);
            h0v    = og * ftanh(cst[0]);
        }
        {
            const float ig = fsig(zi.y + zc[1].x), fg = fsig(zf.y + zc[1].y);
            const float gg = ftanh(zg.y + zc[1].z), og = fsig(zo.y + zc[1].w);
            cst[1] = fmaf(fg, cst[1], ig * gg);
            h1v    = og * ftanh(cst[1]);
        }

        *(float2*)(slab + ((t + 1) & 1) * SLAB_F + unit * 32 + bloc) =
            make_float2(h0v, h1v);
        __syncthreads();
        if (tid == 0) {
            asm volatile("fence.proxy.async.shared::cta;" ::: "memory");
            const uint32_t src  = slab_u32 + (uint32_t)(((t + 1) & 1) * SLAB_F * 4);
            const uint32_t doff = (uint32_t)(((t + 1) & 1) * HBUF_F * 4);
            const uint32_t moff = (uint32_t)(((t + 1) & 1) * 8);
            #pragma unroll
            for (int r = 0; r < CLUSTER; r++) {
                asm volatile(
                    "cp.async.bulk.shared::cluster.shared::cta.mbarrier::complete_tx::bytes "
                    "[%0], [%1], %2, [%3];"
                    :: "r"(dstb[r] + doff), "r"(src), "r"((uint32_t)(SLAB_F * 4)),
                       "r"(mbb[r] + moff) : "memory");
            }
        }
        #pragma unroll
        for (int j = 0; j < 2; j++) zc[j] = zn[j];
    }

    mbar_wait(inbox_u32, (uint32_t)(((TSTEPS - 1) >> 1) & 1));
    asm volatile("barrier.cluster.arrive.aligned;" ::: "memory");

    {
        const int bl = (int)rank * 4 + (wid & 3);     // local batch 0..31
        float s = 0.0f;
        for (int u = lane; u < UNITS; u += 32)
            s += hb[u * HROW + (u >> 6) * HSKEW + bl] * dw[u];
        #pragma unroll
        for (int o = 16; o > 0; o >>= 1)
            s += __shfl_xor_sync(0xffffffffu, s, o);
        const float val = fsig(s + db[0]);
        float* op = out + ((size_t)cid * BB + bl) * TSTEPS + (wid >> 2) * 256;
        for (int i = lane; i < 256; i += 32)
            op[i] = val;
    }
    asm volatile("barrier.cluster.wait.aligned;" ::: "memory");
}

extern "C" void kernel_launch(void* const* d_in, const int* in_sizes, int n_in,
                              void* d_out, int out_size)
{
    const float* x  = (const float*)d_in[0];
    const float* W  = (const float*)d_in[1];
    const float* Uh = (const float*)d_in[2];
    const float* b  = (const float*)d_in[3];
    const float* dw = (const float*)d_in[4];
    const float* db = (const float*)d_in[5];
    float* out = (float*)d_out;

    // one-time host objects (no device memory involved)
    static cudaStream_t s2 = nullptr;
    static cudaEvent_t evFork = nullptr, evJoin = nullptr;
    static int inited = 0, ok = 0;
    if (!inited) {
        inited = 1;
        ok = (cudaStreamCreateWithFlags(&s2, cudaStreamNonBlocking) == cudaSuccess) &&
             (cudaEventCreateWithFlags(&evFork, cudaEventDisableTiming) == cudaSuccess) &&
             (cudaEventCreateWithFlags(&evJoin, cudaEventDisableTiming) == cudaSuccess);
    }

    const size_t rsm = (size_t)(UNITS * NCOLS + 2 * HBUF_F + 2 * SLAB_F) * sizeof(float) + 32;
    cudaFuncSetAttribute(lstm_kernel,
                         cudaFuncAttributeMaxDynamicSharedMemorySize, (int)rsm);

    reset_kernel<<<1, 32>>>();

    if (ok) {
        // head: zx tile 0 on the main stream (full device, ~0.25 ms)
        zx_kernel<<<dim3(8, 512, 1), 256>>>(x, W, b, 0);
        // fork: tail (tiles 1..7) runs concurrently with lstm
        cudaEventRecord(evFork, 0);
        cudaStreamWaitEvent(s2, evFork, 0);
        lstm_kernel<<<NCLUST * CLUSTER, RTHREADS, rsm>>>(Uh, dw, db, out);
        zx_kernel<<<dim3(8, 512, NTILES - 1), 256, 0, s2>>>(x, W, b, 1);
        cudaEventRecord(evJoin, s2);
        cudaStreamWaitEvent(0, evJoin, 0);
    } else {
        // fallback: fully serial (flags trivially satisfied before lstm)
        zx_kernel<<<dim3(8, 512, NTILES), 256>>>(x, W, b, 0);
        lstm_kernel<<<NCLUST * CLUSTER, RTHREADS, rsm>>>(Uh, dw, db, out);
    }
}